// round 10
// baseline (speedup 1.0000x reference)
#include <cuda_runtime.h>

// VoxelMorph SpatialTransformer, trilinear, zero padding.
// Smem-tiled gather v5: 8x4x32 tile => 52.8KB smem => 4 CTAs/SM (2048 thr),
// vectorized fill (LDG.128 + STS.128), channel-interleaved float2 smem,
// int32 indexing, reference-exact rounding.
// src:  [B=2, C=2, 160, 192, 160] f32
// flow: [B=2, 3,   160, 192, 160] f32  (dz, dy, dx)
// out:  [B=2, C=2, 160, 192, 160] f32

namespace {
constexpr int D = 160, H = 192, W = 160, C = 2, B = 2;
constexpr int N  = D * H * W;
constexpr int HW = H * W;

constexpr int TZ = 8, TY = 4, TX = 32;  // output tile (1024 voxels)
constexpr int R  = 3;
constexpr int SZ = TZ + 1 + 2 * R;      // 15 z-slices
constexpr int SY = TY + 1 + 2 * R;      // 11 y-rows
constexpr int SXP = 40;                 // x entries (float2), quad-aligned
constexpr int ROWS = SZ * SY;           // 165
constexpr int QPR  = SXP / 4;           // 10 quads per row
constexpr int SMEM_BYTES = ROWS * SXP * 8;   // 52800
constexpr int NZT = D / TZ;             // 20
constexpr int ZPT = 2;                  // z-planes per thread (4 z thread-groups)
// smem x coordinate: x' = gx - (x_t - 4); valid gather x' in [1, 38]
}

__global__ __launch_bounds__(512, 4)
void st_v9_kernel(const float* __restrict__ src,
                  const float* __restrict__ flow,
                  float* __restrict__ out)
{
    extern __shared__ float2 sm2[];     // [SZ*SY][SXP], .x=ch0 .y=ch1

    const int bzz = blockIdx.z;
    const int b   = bzz / NZT;
    const int z_t = (bzz - b * NZT) * TZ;
    const int y_t = blockIdx.y * TY;
    const int x_t = blockIdx.x * TX;
    const int z_lo = z_t - R, y_lo = y_t - R;
    const int x_al = x_t - 4;           // smem x' = gx - x_al

    const int tid = (threadIdx.z * TY + threadIdx.y) * TX + threadIdx.x;

    const float* s0 = src + b * C * N;
    const float* s1 = s0 + N;

    // ---- fill: (row, quad) units, all-or-nothing quad validity ----
    for (int u = tid; u < ROWS * QPR; u += 512) {
        const int row = u / QPR;
        const int qi  = u - row * QPR;
        const int sz  = row / SY;
        const int sy  = row - sz * SY;
        const int gz  = z_lo + sz;
        const int gy  = y_lo + sy;
        const int gx  = x_al + 4 * qi;  // multiple of 4
        float4 q0 = make_float4(0.f, 0.f, 0.f, 0.f);
        float4 q1 = q0;
        if (((unsigned)gz < (unsigned)D) & ((unsigned)gy < (unsigned)H) &
            ((unsigned)gx < (unsigned)W)) {
            const int off = (gz * H + gy) * W + gx;   // 16B-aligned
            q0 = __ldg((const float4*)(s0 + off));
            q1 = __ldg((const float4*)(s1 + off));
        }
        float4* dst = (float4*)(sm2 + row * SXP + 4 * qi);  // 32B-aligned
        dst[0] = make_float4(q0.x, q1.x, q0.y, q1.y);
        dst[1] = make_float4(q0.z, q1.z, q0.w, q1.w);
    }
    __syncthreads();

    // ---- gather: each thread handles ZPT z-planes ----
    const int h = y_t + threadIdx.y;
    const int w = x_t + threadIdx.x;
    const int z_b = z_t + threadIdx.z * ZPT;

    const float* fb = flow + b * 3 * N;
    float* ob = out + b * C * N;

    int s = (z_b * H + h) * W + w;

    #pragma unroll
    for (int k = 0; k < ZPT; ++k, s += HW) {
        const int d = z_b + k;

        const float zf = (float)d + __ldg(fb + s);
        const float yf = (float)h + __ldg(fb + s + N);
        const float xf = (float)w + __ldg(fb + s + 2 * N);

        const int z0 = __float2int_rd(zf);
        const int y0 = __float2int_rd(yf);
        const int x0 = __float2int_rd(xf);
        const float fz = zf - (float)z0;
        const float fy = yf - (float)y0;
        const float fx = xf - (float)x0;
        const float gz = 1.0f - fz, gy = 1.0f - fy, gx = 1.0f - fx;

        const float w00 = gz * gy, w01 = gz * fy, w10 = fz * gy, w11 = fz * fy;
        const float w000 = w00 * gx, w001 = w00 * fx;
        const float w010 = w01 * gx, w011 = w01 * fx;
        const float w100 = w10 * gx, w101 = w10 * fx;
        const float w110 = w11 * gx, w111 = w11 * fx;

        const int z0l = z0 - z_lo;      // in-tile: [0, SZ-2]
        const int y0l = y0 - y_lo;      // in-tile: [0, SY-2]
        const int x0l = x0 - x_al;      // in-tile: [1, SXP-2]

        float a0, a1;

        if (((unsigned)z0l <= (unsigned)(SZ - 2)) &
            ((unsigned)y0l <= (unsigned)(SY - 2)) &
            ((unsigned)(x0l - 1) <= (unsigned)(SXP - 3))) {
            const float2* p = sm2 + (z0l * SY + y0l) * SXP + x0l;
            const float2 c000 = p[0];
            const float2 c001 = p[1];
            const float2 c010 = p[SXP];
            const float2 c011 = p[SXP + 1];
            const float2 c100 = p[SY * SXP];
            const float2 c101 = p[SY * SXP + 1];
            const float2 c110 = p[SY * SXP + SXP];
            const float2 c111 = p[SY * SXP + SXP + 1];
            a0 = w000 * c000.x + w001 * c001.x
               + w010 * c010.x + w011 * c011.x
               + w100 * c100.x + w101 * c101.x
               + w110 * c110.x + w111 * c111.x;
            a1 = w000 * c000.y + w001 * c001.y
               + w010 * c010.y + w011 * c011.y
               + w100 * c100.y + w101 * c101.y
               + w110 * c110.y + w111 * c111.y;
        } else {
            // rare fallback: sample escapes tile (|flow| > R)
            a0 = 0.0f; a1 = 0.0f;
            #pragma unroll
            for (int dz = 0; dz < 2; ++dz) {
                const int zi = z0 + dz;
                if ((unsigned)zi >= (unsigned)D) continue;
                const float wz = dz ? fz : gz;
                #pragma unroll
                for (int dy = 0; dy < 2; ++dy) {
                    const int yi = y0 + dy;
                    if ((unsigned)yi >= (unsigned)H) continue;
                    const float wzy = wz * (dy ? fy : gy);
                    #pragma unroll
                    for (int dx = 0; dx < 2; ++dx) {
                        const int xi = x0 + dx;
                        if ((unsigned)xi >= (unsigned)W) continue;
                        const float wgt = wzy * (dx ? fx : gx);
                        const int lin = (zi * H + yi) * W + xi;
                        a0 += wgt * __ldg(s0 + lin);
                        a1 += wgt * __ldg(s1 + lin);
                    }
                }
            }
        }

        ob[s]     = a0;
        ob[s + N] = a1;
    }
}

extern "C" void kernel_launch(void* const* d_in, const int* in_sizes, int n_in,
                              void* d_out, int out_size)
{
    const float* src  = (const float*)d_in[0];
    const float* flow = (const float*)d_in[1];
    float* out = (float*)d_out;

    static bool attr_done = false;
    if (!attr_done) {
        cudaFuncSetAttribute(st_v9_kernel,
                             cudaFuncAttributeMaxDynamicSharedMemorySize,
                             SMEM_BYTES);
        attr_done = true;
    }

    dim3 block(TX, TY, 4);                  // 512 threads
    dim3 grid(W / TX, H / TY, B * NZT);     // 5, 48, 40
    st_v9_kernel<<<grid, block, SMEM_BYTES>>>(src, flow, out);
}

// round 11
// speedup vs baseline: 1.1961x; 1.1961x over previous
#include <cuda_runtime.h>

// VoxelMorph SpatialTransformer, trilinear, zero padding.
// Smem-tiled gather v6: 16x8x32 tile (110.4KB smem), 1024-thread CTAs,
// 2 CTAs/SM = 2048 threads (max occupancy) at the lowest halo amplification
// (3.37x). Vectorized fill (LDG.128 + STS.128), channel-interleaved float2
// smem, int32 indexing, reference-exact rounding.
// src:  [B=2, C=2, 160, 192, 160] f32
// flow: [B=2, 3,   160, 192, 160] f32  (dz, dy, dx)
// out:  [B=2, C=2, 160, 192, 160] f32

namespace {
constexpr int D = 160, H = 192, W = 160, C = 2, B = 2;
constexpr int N  = D * H * W;
constexpr int HW = H * W;

constexpr int TZ = 16, TY = 8, TX = 32; // output tile (4096 voxels)
constexpr int R  = 3;
constexpr int SZ = TZ + 1 + 2 * R;      // 23 z-slices
constexpr int SY = TY + 1 + 2 * R;      // 15 y-rows
constexpr int SXP = 40;                 // x entries (float2), quad-aligned
constexpr int ROWS = SZ * SY;           // 345
constexpr int QPR  = SXP / 4;           // 10 quads per row
constexpr int SMEM_BYTES = ROWS * SXP * 8;   // 110400
constexpr int NZT = D / TZ;             // 10
constexpr int ZPT = 4;                  // z-planes per thread (4 z thread-groups)
constexpr int NTHREADS = 1024;
// smem x coordinate: x' = gx - (x_t - 4); valid gather x' in [1, 38]
}

__global__ __launch_bounds__(NTHREADS, 2)
void st_v10_kernel(const float* __restrict__ src,
                   const float* __restrict__ flow,
                   float* __restrict__ out)
{
    extern __shared__ float2 sm2[];     // [SZ*SY][SXP], .x=ch0 .y=ch1

    const int bzz = blockIdx.z;
    const int b   = bzz / NZT;
    const int z_t = (bzz - b * NZT) * TZ;
    const int y_t = blockIdx.y * TY;
    const int x_t = blockIdx.x * TX;
    const int z_lo = z_t - R, y_lo = y_t - R;
    const int x_al = x_t - 4;           // smem x' = gx - x_al

    const int tid = (threadIdx.z * TY + threadIdx.y) * TX + threadIdx.x;

    const float* s0 = src + b * C * N;
    const float* s1 = s0 + N;

    // ---- fill: (row, quad) units, all-or-nothing quad validity ----
    for (int u = tid; u < ROWS * QPR; u += NTHREADS) {
        const int row = u / QPR;
        const int qi  = u - row * QPR;
        const int sz  = row / SY;
        const int sy  = row - sz * SY;
        const int gz  = z_lo + sz;
        const int gy  = y_lo + sy;
        const int gx  = x_al + 4 * qi;  // multiple of 4
        float4 q0 = make_float4(0.f, 0.f, 0.f, 0.f);
        float4 q1 = q0;
        if (((unsigned)gz < (unsigned)D) & ((unsigned)gy < (unsigned)H) &
            ((unsigned)gx < (unsigned)W)) {
            const int off = (gz * H + gy) * W + gx;   // 16B-aligned
            q0 = __ldg((const float4*)(s0 + off));
            q1 = __ldg((const float4*)(s1 + off));
        }
        float4* dst = (float4*)(sm2 + row * SXP + 4 * qi);  // 32B-aligned
        dst[0] = make_float4(q0.x, q1.x, q0.y, q1.y);
        dst[1] = make_float4(q0.z, q1.z, q0.w, q1.w);
    }
    __syncthreads();

    // ---- gather: each thread handles ZPT z-planes ----
    const int h = y_t + threadIdx.y;
    const int w = x_t + threadIdx.x;
    const int z_b = z_t + threadIdx.z * ZPT;

    const float* fb = flow + b * 3 * N;
    float* ob = out + b * C * N;

    int s = (z_b * H + h) * W + w;

    #pragma unroll
    for (int k = 0; k < ZPT; ++k, s += HW) {
        const int d = z_b + k;

        const float zf = (float)d + __ldg(fb + s);
        const float yf = (float)h + __ldg(fb + s + N);
        const float xf = (float)w + __ldg(fb + s + 2 * N);

        const int z0 = __float2int_rd(zf);
        const int y0 = __float2int_rd(yf);
        const int x0 = __float2int_rd(xf);
        const float fz = zf - (float)z0;
        const float fy = yf - (float)y0;
        const float fx = xf - (float)x0;
        const float gz = 1.0f - fz, gy = 1.0f - fy, gx = 1.0f - fx;

        const float w00 = gz * gy, w01 = gz * fy, w10 = fz * gy, w11 = fz * fy;
        const float w000 = w00 * gx, w001 = w00 * fx;
        const float w010 = w01 * gx, w011 = w01 * fx;
        const float w100 = w10 * gx, w101 = w10 * fx;
        const float w110 = w11 * gx, w111 = w11 * fx;

        const int z0l = z0 - z_lo;      // in-tile: [0, SZ-2]
        const int y0l = y0 - y_lo;      // in-tile: [0, SY-2]
        const int x0l = x0 - x_al;      // in-tile: [1, SXP-2]

        float a0, a1;

        if (((unsigned)z0l <= (unsigned)(SZ - 2)) &
            ((unsigned)y0l <= (unsigned)(SY - 2)) &
            ((unsigned)(x0l - 1) <= (unsigned)(SXP - 3))) {
            const float2* p = sm2 + (z0l * SY + y0l) * SXP + x0l;
            const float2 c000 = p[0];
            const float2 c001 = p[1];
            const float2 c010 = p[SXP];
            const float2 c011 = p[SXP + 1];
            const float2 c100 = p[SY * SXP];
            const float2 c101 = p[SY * SXP + 1];
            const float2 c110 = p[SY * SXP + SXP];
            const float2 c111 = p[SY * SXP + SXP + 1];
            a0 = w000 * c000.x + w001 * c001.x
               + w010 * c010.x + w011 * c011.x
               + w100 * c100.x + w101 * c101.x
               + w110 * c110.x + w111 * c111.x;
            a1 = w000 * c000.y + w001 * c001.y
               + w010 * c010.y + w011 * c011.y
               + w100 * c100.y + w101 * c101.y
               + w110 * c110.y + w111 * c111.y;
        } else {
            // rare fallback: sample escapes tile (|flow| > R)
            a0 = 0.0f; a1 = 0.0f;
            #pragma unroll
            for (int dz = 0; dz < 2; ++dz) {
                const int zi = z0 + dz;
                if ((unsigned)zi >= (unsigned)D) continue;
                const float wz = dz ? fz : gz;
                #pragma unroll
                for (int dy = 0; dy < 2; ++dy) {
                    const int yi = y0 + dy;
                    if ((unsigned)yi >= (unsigned)H) continue;
                    const float wzy = wz * (dy ? fy : gy);
                    #pragma unroll
                    for (int dx = 0; dx < 2; ++dx) {
                        const int xi = x0 + dx;
                        if ((unsigned)xi >= (unsigned)W) continue;
                        const float wgt = wzy * (dx ? fx : gx);
                        const int lin = (zi * H + yi) * W + xi;
                        a0 += wgt * __ldg(s0 + lin);
                        a1 += wgt * __ldg(s1 + lin);
                    }
                }
            }
        }

        ob[s]     = a0;
        ob[s + N] = a1;
    }
}

extern "C" void kernel_launch(void* const* d_in, const int* in_sizes, int n_in,
                              void* d_out, int out_size)
{
    const float* src  = (const float*)d_in[0];
    const float* flow = (const float*)d_in[1];
    float* out = (float*)d_out;

    static bool attr_done = false;
    if (!attr_done) {
        cudaFuncSetAttribute(st_v10_kernel,
                             cudaFuncAttributeMaxDynamicSharedMemorySize,
                             SMEM_BYTES);
        attr_done = true;
    }

    dim3 block(TX, TY, 4);                  // 1024 threads
    dim3 grid(W / TX, H / TY, B * NZT);     // 5, 24, 20
    st_v10_kernel<<<grid, block, SMEM_BYTES>>>(src, flow, out);
}